// round 11
// baseline (speedup 1.0000x reference)
#include <cuda_runtime.h>
#include <cuda_fp16.h>
#include <cstdint>

#define TT 4096
#define BATCH 64
#define HH 512
#define GRID 64
#define NTH 256
#define NFLAGS 256      // one per (CTA, warp-pair)
#define KSTEPS 36
#define RSB 1168        // row stride bytes (584 halves, padded)
#define SGS 20          // gate staging stride (floats, even + conflict-friendly)

// smem byte offsets
#define OFF_BIAS 0              // 32 f32 = 128
#define OFF_G    128            // 4 pairs x 32x20 f32 = 10240
#define OFF_P    10368          // 4 pairs x 16x8 half = 1024
#define OFF_O    11392          // 4 pairs x 16x8 f32  = 2048
#define OFF_A    13440          // 32 x 584 f16 = 37376
#define OFF_B    50816          // 4 pairs x 16 x 1168 = 74752
#define SMEM_TOTAL 125568

__device__ __align__(16) __half g_hh[2][BATCH*HH];
__device__ int g_flags[NFLAGS];

__device__ __forceinline__ float sigf(float x){ return 1.f/(1.f+__expf(-x)); }
__device__ __forceinline__ float tanhf_fast(float x){
    float e = __expf(-2.f*fabsf(x));
    return copysignf((1.f-e)/(1.f+e), x);
}
__device__ __forceinline__ unsigned pack2h(float a, float b){
    __half2 h = __floats2half2_rn(a, b);
    return *reinterpret_cast<unsigned*>(&h);
}
__device__ __forceinline__ void cp16(unsigned dst, const void* src){
    asm volatile("cp.async.cg.shared.global [%0], [%1], 16;\n"::"r"(dst),"l"(src));
}
__device__ __forceinline__ void cp_commit(){ asm volatile("cp.async.commit_group;\n"::); }
#define CP_WAIT(N) asm volatile("cp.async.wait_group %0;\n"::"n"(N))

__device__ __forceinline__ unsigned smem_u32(const void* p){
    unsigned a;
    asm("{ .reg .u64 t; cvta.to.shared.u64 t, %1; cvt.u32.u64 %0, t; }" : "=r"(a) : "l"(p));
    return a;
}
#define PAIR_BAR(id) asm volatile("bar.sync %0, 64;" :: "r"(id) : "memory")

#define LDSM4(r0,r1,r2,r3,addr) \
    asm volatile("ldmatrix.sync.aligned.m8n8.x4.shared.b16 {%0,%1,%2,%3}, [%4];" \
        : "=r"(r0),"=r"(r1),"=r"(r2),"=r"(r3) : "r"(addr))

#define MMA16816(d,a0,a1,a2,a3,b0,b1) \
    asm volatile("mma.sync.aligned.m16n8k16.row.col.f32.f16.f16.f32 " \
        "{%0,%1,%2,%3}, {%4,%5,%6,%7}, {%8,%9}, {%0,%1,%2,%3};" \
        : "+f"((d)[0]),"+f"((d)[1]),"+f"((d)[2]),"+f"((d)[3]) \
        : "r"(a0),"r"(a1),"r"(a2),"r"(a3),"r"(b0),"r"(b1))

__global__ void __launch_bounds__(128,1) stn_init_kernel(){
    int i = blockIdx.x*blockDim.x + threadIdx.x;
    if (i < 2*BATCH*HH/8)
        reinterpret_cast<uint4*>(g_hh)[i] = make_uint4(0,0,0,0);
    if (i < NFLAGS) g_flags[i] = 0;
}

__global__ void __launch_bounds__(NTH,1) stn_kernel(
    const float* __restrict__ x,      // [64,4096,64]
    const float* __restrict__ W_ih,   // [2048,64]
    const float* __restrict__ W_hh,   // [2048,512]
    const float* __restrict__ b_ih,
    const float* __restrict__ b_hh,
    float* __restrict__ out_states,   // [64,4096,512]
    float* __restrict__ out_final)    // [64,1024]
{
    extern __shared__ __align__(16) unsigned char smem[];
    float* sBias = reinterpret_cast<float*>(smem + OFF_BIAS);
    const unsigned S = smem_u32(smem);

    const int tid  = threadIdx.x;
    const int lane = tid & 31, warp = tid >> 5;
    const int U0   = blockIdx.x * 8;

    // ---- weights once: local row r = gate*8+u -> global row gate*512 + U0 + u
    for (int idx = tid; idx < 32*72; idx += NTH){
        int r = idx / 72, c8 = (idx - r*72) * 8;
        int R = (r >> 3)*HH + U0 + (r & 7);
        const float* src = (c8 < HH) ? (W_hh + (size_t)R*HH + c8)
                                     : (W_ih + R*64 + (c8 - HH));
        float4 v0 = *reinterpret_cast<const float4*>(src);
        float4 v1 = *reinterpret_cast<const float4*>(src + 4);
        uint4 pk;
        pk.x = pack2h(v0.x, v0.y); pk.y = pack2h(v0.z, v0.w);
        pk.z = pack2h(v1.x, v1.y); pk.w = pack2h(v1.z, v1.w);
        *reinterpret_cast<uint4*>(smem + OFF_A + r*RSB + c8*2) = pk;
    }
    if (tid < 32){
        int R = (tid >> 3)*HH + U0 + (tid & 7);
        sBias[tid] = b_ih[R] + b_hh[R];
    }
    __syncthreads();      // only block-wide sync in the kernel

    // ---- roles
    const int pair  = warp & 3;          // N tile: batches pair*16 .. +15
    const int hi    = warp >> 2;         // 0: gate rows 0-15 (i,f); 1: rows 16-31 (g,o)
    const int rbase = hi * 8;            // this warp's 8 batch rows within pair region
    const int mrow0 = hi * 16;
    const int gb0   = pair*16 + rbase;   // first global batch owned by this warp
    const int barid = pair + 1;

    float* sG = reinterpret_cast<float*>(smem + OFF_G) + pair*32*SGS;
    __half* sP = reinterpret_cast<__half*>(smem + OFF_P) + pair*128;
    float*  sO = reinterpret_cast<float*>(smem + OFF_O) + pair*128;
    unsigned char* sBgen = smem + OFF_B + pair*16*RSB;
    const unsigned sBp   = S + OFF_B + pair*16*RSB;
    const unsigned aAddr = S + OFF_A + (unsigned)(mrow0 + (lane & 15))*RSB + (lane >> 4)*16;
    const unsigned bAddr = sBp + (unsigned)(lane & 15)*RSB + (lane >> 4)*16;

    const int xb = lane >> 2, xq = lane & 3;    // x load: batch gb0+xb, col group xq
    const int eu = lane & 3,  eb = lane >> 2;   // epilogue: units eu,eu+4; batch col rbase+eb
    const int ecol = rbase + eb;
    const int egb  = pair*16 + ecol;

    float cA = 0.f, cB = 0.f, hA = 0.f, hB = 0.f;

    for (int t = 0; t < TT; ++t){
        // ---- x prefetch (before flag wait, hides DRAM latency)
        const float* xp = x + ((size_t)(gb0 + xb)*TT + t)*64 + xq*16;
        float4 x0 = *reinterpret_cast<const float4*>(xp);
        float4 x1 = *reinterpret_cast<const float4*>(xp + 4);
        float4 x2 = *reinterpret_cast<const float4*>(xp + 8);
        float4 x3 = *reinterpret_cast<const float4*>(xp + 12);

        // ---- per-warp wait: all 256 pair-flags >= t (relaxed polls + acquire fence)
        if (t){
            unsigned ok;
            do {
                ok = 1u;
#pragma unroll
                for (int i = 0; i < 8; ++i){
                    unsigned v;
                    asm volatile("ld.relaxed.gpu.global.u32 %0, [%1];"
                                 : "=r"(v) : "l"(&g_flags[lane + 32*i]) : "memory");
                    ok &= (unsigned)(v >= (unsigned)t);
                }
            } while (!ok);
            asm volatile("fence.acq_rel.gpu;" ::: "memory");
        }

        // ---- cp.async this warp's 8 batch rows, 2 K-chunks
        const unsigned char* hsrc = reinterpret_cast<const unsigned char*>(g_hh[t & 1]);
#pragma unroll
        for (int i = 0; i < 8; ++i){
            int idx = i*32 + lane;               // 0..255
            int rr = idx >> 5, ch = idx & 31;    // row 0..7, 16B chunk 0..31 (cols 0-255)
            cp16(sBp + (unsigned)(rbase + rr)*RSB + ch*16,
                 hsrc + (size_t)(gb0 + rr)*1024 + ch*16);
        }
        cp_commit();
#pragma unroll
        for (int i = 0; i < 8; ++i){
            int idx = i*32 + lane;
            int rr = idx >> 5, ch = idx & 31;    // cols 256-511
            cp16(sBp + (unsigned)(rbase + rr)*RSB + 512 + ch*16,
                 hsrc + (size_t)(gb0 + rr)*1024 + 512 + ch*16);
        }
        cp_commit();

        // ---- stage x (cols 512..575) for this warp's 8 batches
        {
            uint4 p0, p1;
            p0.x = pack2h(x0.x,x0.y); p0.y = pack2h(x0.z,x0.w);
            p0.z = pack2h(x1.x,x1.y); p0.w = pack2h(x1.z,x1.w);
            p1.x = pack2h(x2.x,x2.y); p1.y = pack2h(x2.z,x2.w);
            p1.z = pack2h(x3.x,x3.y); p1.w = pack2h(x3.z,x3.w);
            unsigned char* dst = sBgen + (unsigned)(rbase + xb)*RSB + 1024 + xq*32;
            *reinterpret_cast<uint4*>(dst)      = p0;
            *reinterpret_cast<uint4*>(dst + 16) = p1;
        }

        float d0[4] = {0.f,0.f,0.f,0.f};
        float d1[4] = {0.f,0.f,0.f,0.f};

        CP_WAIT(1);
        PAIR_BAR(barid);         // partner's chunk-0 + both x stagings visible
#pragma unroll
        for (int ks = 0; ks < 16; ++ks){
            unsigned a0,a1,a2,a3,b0,b1,b2,b3;
            LDSM4(a0,a1,a2,a3, aAddr + ks*32);
            LDSM4(b0,b1,b2,b3, bAddr + ks*32);
            MMA16816(d0, a0,a1,a2,a3, b0,b2);
            MMA16816(d1, a0,a1,a2,a3, b1,b3);
        }
        CP_WAIT(0);
        PAIR_BAR(barid);
#pragma unroll
        for (int ks = 16; ks < KSTEPS; ++ks){
            unsigned a0,a1,a2,a3,b0,b1,b2,b3;
            LDSM4(a0,a1,a2,a3, aAddr + ks*32);
            LDSM4(b0,b1,b2,b3, bAddr + ks*32);
            MMA16816(d0, a0,a1,a2,a3, b0,b2);
            MMA16816(d1, a0,a1,a2,a3, b1,b3);
        }

        // ---- fragments -> pair gate staging
        {
            int fr = mrow0 + (lane >> 2), fc = (lane & 3)*2;
            *reinterpret_cast<float2*>(sG + fr*SGS + fc)       = make_float2(d0[0], d0[1]);
            *reinterpret_cast<float2*>(sG + (fr+8)*SGS + fc)   = make_float2(d0[2], d0[3]);
            *reinterpret_cast<float2*>(sG + fr*SGS + fc+8)     = make_float2(d1[0], d1[1]);
            *reinterpret_cast<float2*>(sG + (fr+8)*SGS + fc+8) = make_float2(d1[2], d1[3]);
        }
        PAIR_BAR(barid);

        // ---- epilogue: cells (eu, ecol) and (eu+4, ecol)
#pragma unroll
        for (int hc = 0; hc < 2; ++hc){
            int u = eu + hc*4;
            float gi = sG[(     u)*SGS + ecol] + sBias[u];
            float gf = sG[( 8 + u)*SGS + ecol] + sBias[ 8 + u];
            float gg = sG[(16 + u)*SGS + ecol] + sBias[16 + u];
            float go = sG[(24 + u)*SGS + ecol] + sBias[24 + u];
            float iv = sigf(gi), fv = sigf(gf);
            float gv = tanhf_fast(gg), ov = sigf(go);
            float cold = hc ? cB : cA;
            float hold = hc ? hB : hA;
            float cn = fv*cold + iv*gv;
            float hn = ov*tanhf_fast(cn);
            float h2 = 0.5f*(hold + hn);        // K = 0.5 Euler blend
            float c2 = 0.5f*(cold + cn);
            if (hc){ cB = c2; hB = h2; } else { cA = c2; hA = h2; }
            sP[ecol*8 + u] = __float2half_rn(h2);
            sO[ecol*8 + u] = h2;
            if (t == TT-1){
                out_final[(size_t)egb*1024 +       U0 + u] = h2;
                out_final[(size_t)egb*1024 + 512 + U0 + u] = c2;
            }
        }
        __syncwarp();

        // ---- publish this warp's 8 batch rows of the next h image
        if (lane < 8){
            int bp = rbase + lane, gb = pair*16 + bp;
            uint4 vh = *reinterpret_cast<uint4*>(sP + bp*8);
            *reinterpret_cast<uint4*>(g_hh[(t+1)&1] + (size_t)gb*HH + U0) = vh;
        }
        PAIR_BAR(barid);          // both warps' publishes done
        if (hi == 0 && lane == 0){
            asm volatile("st.release.gpu.global.u32 [%0], %1;"
                         :: "l"(&g_flags[blockIdx.x*4 + pair]), "r"((unsigned)(t+1)) : "memory");
        }

        // ---- step output stores: off the critical path (after flag release)
        if (lane < 8){
            int bp = rbase + lane, gb = pair*16 + bp;
            float4 v0 = *reinterpret_cast<float4*>(sO + bp*8);
            float4 v1 = *reinterpret_cast<float4*>(sO + bp*8 + 4);
            float* dst = out_states + ((size_t)gb*TT + t)*HH + U0;
            *reinterpret_cast<float4*>(dst)     = v0;
            *reinterpret_cast<float4*>(dst + 4) = v1;
        }
    }
}

extern "C" void kernel_launch(void* const* d_in, const int* in_sizes, int n_in,
                              void* d_out, int out_size)
{
    const float* x    = (const float*)d_in[0];
    const float* W_ih = (const float*)d_in[1];
    const float* W_hh = (const float*)d_in[2];
    const float* b_ih = (const float*)d_in[3];
    const float* b_hh = (const float*)d_in[4];
    float* out        = (float*)d_out;
    float* out_final  = out + (size_t)BATCH*TT*HH;

    cudaFuncSetAttribute(stn_kernel, cudaFuncAttributeMaxDynamicSharedMemorySize, SMEM_TOTAL);
    stn_init_kernel<<<64, 128>>>();
    stn_kernel<<<GRID, NTH, SMEM_TOTAL>>>(x, W_ih, W_hh, b_ih, b_hh, out, out_final);
}

// round 12
// speedup vs baseline: 1.7045x; 1.7045x over previous
#include <cuda_runtime.h>
#include <cuda_fp16.h>
#include <cstdint>

#define TT 4096
#define BATCH 64
#define HH 512
#define GRID 64
#define NTH 256
#define RSB 1168        // A/B row stride bytes (584 halves, padded)
#define SGS 66          // gate staging stride (floats)

// smem byte offsets
#define OFF_BIAS 0              // 32 f32
#define OFF_P    128            // h2 half staging [64][8] = 1024B
#define OFF_O    1152           // h2 f32 staging [64][8] = 2048B
#define OFF_G    3200           // k0 gates [32][66] f32 = 8448
#define OFF_G2   11648          // k1 gates [32][66] f32 = 8448
#define OFF_A    20096          // [32][584] f16 = 37376
#define OFF_B    57472          // [64][584] f16 = 74752
#define SMEM_TOTAL 132224

__device__ __align__(16) __half g_hh[2][BATCH*HH];
__device__ int g_flags[GRID];

__device__ __forceinline__ float sigf(float x){ return 1.f/(1.f+__expf(-x)); }
__device__ __forceinline__ float tanhf_fast(float x){
    float e = __expf(-2.f*fabsf(x));
    return copysignf((1.f-e)/(1.f+e), x);
}
__device__ __forceinline__ unsigned pack2h(float a, float b){
    __half2 h = __floats2half2_rn(a, b);
    return *reinterpret_cast<unsigned*>(&h);
}
__device__ __forceinline__ void cp16(unsigned dst, const void* src){
    asm volatile("cp.async.cg.shared.global [%0], [%1], 16;\n"::"r"(dst),"l"(src));
}
__device__ __forceinline__ void cp_commit(){ asm volatile("cp.async.commit_group;\n"::); }
#define CP_WAIT0() asm volatile("cp.async.wait_group 0;\n"::)

__device__ __forceinline__ unsigned smem_u32(const void* p){
    unsigned a;
    asm("{ .reg .u64 t; cvta.to.shared.u64 t, %1; cvt.u32.u64 %0, t; }" : "=r"(a) : "l"(p));
    return a;
}
#define GBAR(id) asm volatile("bar.sync %0, 128;" :: "r"(id) : "memory")

#define LDSM4(r0,r1,r2,r3,addr) \
    asm volatile("ldmatrix.sync.aligned.m8n8.x4.shared.b16 {%0,%1,%2,%3}, [%4];" \
        : "=r"(r0),"=r"(r1),"=r"(r2),"=r"(r3) : "r"(addr))

#define MMA16816(d,a0,a1,a2,a3,b0,b1) \
    asm volatile("mma.sync.aligned.m16n8k16.row.col.f32.f16.f16.f32 " \
        "{%0,%1,%2,%3}, {%4,%5,%6,%7}, {%8,%9}, {%0,%1,%2,%3};" \
        : "+f"((d)[0]),"+f"((d)[1]),"+f"((d)[2]),"+f"((d)[3]) \
        : "r"(a0),"r"(a1),"r"(a2),"r"(a3),"r"(b0),"r"(b1))

__global__ void __launch_bounds__(128,1) stn_init_kernel(){
    int i = blockIdx.x*blockDim.x + threadIdx.x;
    if (i < 2*BATCH*HH/8)
        reinterpret_cast<uint4*>(g_hh)[i] = make_uint4(0,0,0,0);
    if (i < GRID) g_flags[i] = 0;
}

__device__ __forceinline__ void poll_flag(const int* fp, unsigned t){
    unsigned v;
    do {
        asm volatile("ld.relaxed.gpu.global.u32 %0, [%1];" : "=r"(v) : "l"(fp) : "memory");
    } while (v < t);
    asm volatile("fence.acq_rel.gpu;" ::: "memory");
}

__global__ void __launch_bounds__(NTH,1) stn_kernel(
    const float* __restrict__ x,      // [64,4096,64]
    const float* __restrict__ W_ih,   // [2048,64]
    const float* __restrict__ W_hh,   // [2048,512]
    const float* __restrict__ b_ih,
    const float* __restrict__ b_hh,
    float* __restrict__ out_states,   // [64,4096,512]
    float* __restrict__ out_final)    // [64,1024]
{
    extern __shared__ __align__(16) unsigned char smem[];
    float*  sBias = reinterpret_cast<float*>(smem + OFF_BIAS);
    __half* sHI   = reinterpret_cast<__half*>(smem + OFF_P);
    float*  sOUT  = reinterpret_cast<float*>(smem + OFF_O);
    float*  sG    = reinterpret_cast<float*>(smem + OFF_G);
    float*  sG2   = reinterpret_cast<float*>(smem + OFF_G2);
    const unsigned S = smem_u32(smem);
    const unsigned sB = S + OFF_B;

    const int tid  = threadIdx.x;
    const int lane = tid & 31, warp = tid >> 5;
    const int U0   = blockIdx.x * 8;

    // ---- weights once: local row r = gate*8+u -> global row gate*512 + U0 + u
    for (int idx = tid; idx < 32*72; idx += NTH){
        int r = idx / 72, c8 = (idx - r*72) * 8;
        int R = (r >> 3)*HH + U0 + (r & 7);
        const float* src = (c8 < HH) ? (W_hh + (size_t)R*HH + c8)
                                     : (W_ih + R*64 + (c8 - HH));
        float4 v0 = *reinterpret_cast<const float4*>(src);
        float4 v1 = *reinterpret_cast<const float4*>(src + 4);
        uint4 pk;
        pk.x = pack2h(v0.x, v0.y); pk.y = pack2h(v0.z, v0.w);
        pk.z = pack2h(v1.x, v1.y); pk.w = pack2h(v1.z, v1.w);
        *reinterpret_cast<uint4*>(smem + OFF_A + r*RSB + c8*2) = pk;
    }
    if (tid < 32){
        int R = (tid >> 3)*HH + U0 + (tid & 7);
        sBias[tid] = b_ih[R] + b_hh[R];
    }
    __syncthreads();

    // ---- warp roles: kg = k-half, (mrow0, nc0) = 16x32 output tile
    const int kg    = warp >> 2;          // 0: k cols 0-287, 1: 288-575 (incl x)
    const int wl    = warp & 3;
    const int mrow0 = (wl & 1) * 16;
    const int nc0   = (wl >> 1) * 32;
    const int kbase = kg * 18;
    const int barid = kg + 1;
    const int gt    = tid & 127;          // tid within group

    const unsigned aAddr  = S + OFF_A + (unsigned)(mrow0 + (lane & 15))*RSB + (lane >> 4)*16 + kbase*32;
    const unsigned bAddr0 = sB + (unsigned)(nc0      + (lane & 15))*RSB + (lane >> 4)*16 + kbase*32;
    const unsigned bAddr1 = sB + (unsigned)(nc0 + 16 + (lane & 15))*RSB + (lane >> 4)*16 + kbase*32;

    // ---- preload constant A fragments (72 regs)
    unsigned Af[18][4];
#pragma unroll
    for (int ks = 0; ks < 18; ++ks)
        LDSM4(Af[ks][0], Af[ks][1], Af[ks][2], Af[ks][3], aAddr + ks*32);

    float* sGk = (kg == 0) ? sG : sG2;

    // cp roles within group: row = gt>>1, half = gt&1
    const int cprow = gt >> 1, cphalf = gt & 1;
    // x roles (k1 group only): batch xb, 32-col half xh
    const int xb = gt >> 1, xh = gt & 1;
    // epilogue roles
    const int eu = tid & 7, eb0 = tid >> 3;       // unit, batch base (0..31)

    float cA = 0.f, cB = 0.f, hA = 0.f, hB = 0.f;

    for (int t = 0; t < TT; ++t){
        const int par = t & 1;
        const __half* hsrc = g_hh[par];

        if (kg == 0){
            // ---- wait producer CTAs 0..35 (units 0..287)
            if (tid < 36) poll_flag(&g_flags[tid], (unsigned)t);
            GBAR(1);
            // ---- cp chunk0: cols 0..287 (576B per row, split in 2 halves)
            {
                const unsigned char* src = reinterpret_cast<const unsigned char*>(hsrc)
                                         + (size_t)cprow*1024 + cphalf*288;
                unsigned dst = sB + (unsigned)cprow*RSB + cphalf*288;
#pragma unroll
                for (int i = 0; i < 18; ++i) cp16(dst + i*16, src + i*16);
            }
            cp_commit();
            CP_WAIT0();
            GBAR(1);
        } else {
            // ---- x prefetch (32 floats) before poll
            const float* xp = x + ((size_t)xb*TT + t)*64 + xh*32;
            float4 xr[8];
#pragma unroll
            for (int i = 0; i < 8; ++i) xr[i] = *reinterpret_cast<const float4*>(xp + i*4);

            // ---- wait producer CTAs 36..63 (units 288..511)
            if (gt < 28) poll_flag(&g_flags[36 + gt], (unsigned)t);
            GBAR(2);
            // ---- cp chunk1: cols 288..511 (448B per row, split in 2 halves)
            {
                const unsigned char* src = reinterpret_cast<const unsigned char*>(hsrc)
                                         + (size_t)cprow*1024 + 576 + cphalf*224;
                unsigned dst = sB + (unsigned)cprow*RSB + 576 + cphalf*224;
#pragma unroll
                for (int i = 0; i < 14; ++i) cp16(dst + i*16, src + i*16);
            }
            cp_commit();
            // ---- stage x (cols 512..575): 32 halves = 4 uint4
            {
                uint4 p0, p1;
                p0.x = pack2h(xr[0].x,xr[0].y); p0.y = pack2h(xr[0].z,xr[0].w);
                p0.z = pack2h(xr[1].x,xr[1].y); p0.w = pack2h(xr[1].z,xr[1].w);
                p1.x = pack2h(xr[2].x,xr[2].y); p1.y = pack2h(xr[2].z,xr[2].w);
                p1.z = pack2h(xr[3].x,xr[3].y); p1.w = pack2h(xr[3].z,xr[3].w);
                unsigned char* dst = smem + OFF_B + (unsigned)xb*RSB + 1024 + xh*64;
                *reinterpret_cast<uint4*>(dst)      = p0;
                *reinterpret_cast<uint4*>(dst + 16) = p1;
                p0.x = pack2h(xr[4].x,xr[4].y); p0.y = pack2h(xr[4].z,xr[4].w);
                p0.z = pack2h(xr[5].x,xr[5].y); p0.w = pack2h(xr[5].z,xr[5].w);
                p1.x = pack2h(xr[6].x,xr[6].y); p1.y = pack2h(xr[6].z,xr[6].w);
                p1.z = pack2h(xr[7].x,xr[7].y); p1.w = pack2h(xr[7].z,xr[7].w);
                *reinterpret_cast<uint4*>(dst + 32) = p0;
                *reinterpret_cast<uint4*>(dst + 48) = p1;
            }
            CP_WAIT0();
            GBAR(2);
        }

        // ---- MMA: 18 k-steps, B-only LDSM, A from registers
        float d0[4] = {0.f,0.f,0.f,0.f};
        float d1[4] = {0.f,0.f,0.f,0.f};
        float d2[4] = {0.f,0.f,0.f,0.f};
        float d3[4] = {0.f,0.f,0.f,0.f};
#pragma unroll
        for (int ks = 0; ks < 18; ++ks){
            unsigned b0,b1,b2,b3,b4,b5,b6,b7;
            LDSM4(b0,b1,b2,b3, bAddr0 + ks*32);
            LDSM4(b4,b5,b6,b7, bAddr1 + ks*32);
            MMA16816(d0, Af[ks][0],Af[ks][1],Af[ks][2],Af[ks][3], b0,b2);
            MMA16816(d1, Af[ks][0],Af[ks][1],Af[ks][2],Af[ks][3], b1,b3);
            MMA16816(d2, Af[ks][0],Af[ks][1],Af[ks][2],Af[ks][3], b4,b6);
            MMA16816(d3, Af[ks][0],Af[ks][1],Af[ks][2],Af[ks][3], b5,b7);
        }

        // ---- fragments -> this k-half's gate buffer
        {
            int fr = mrow0 + (lane >> 2), fc = nc0 + (lane & 3)*2;
            *reinterpret_cast<float2*>(sGk + fr*SGS + fc)        = make_float2(d0[0], d0[1]);
            *reinterpret_cast<float2*>(sGk + (fr+8)*SGS + fc)    = make_float2(d0[2], d0[3]);
            *reinterpret_cast<float2*>(sGk + fr*SGS + fc+8)      = make_float2(d1[0], d1[1]);
            *reinterpret_cast<float2*>(sGk + (fr+8)*SGS + fc+8)  = make_float2(d1[2], d1[3]);
            *reinterpret_cast<float2*>(sGk + fr*SGS + fc+16)     = make_float2(d2[0], d2[1]);
            *reinterpret_cast<float2*>(sGk + (fr+8)*SGS + fc+16) = make_float2(d2[2], d2[3]);
            *reinterpret_cast<float2*>(sGk + fr*SGS + fc+24)     = make_float2(d3[0], d3[1]);
            *reinterpret_cast<float2*>(sGk + (fr+8)*SGS + fc+24) = make_float2(d3[2], d3[3]);
        }
        __syncthreads();

        // ---- epilogue: 2 cells per thread: (eu, eb0) and (eu, eb0+32)
#pragma unroll
        for (int half = 0; half < 2; ++half){
            int b = eb0 + half*32;
            float gi = sG[(     eu)*SGS + b] + sG2[(     eu)*SGS + b] + sBias[eu];
            float gf = sG[( 8 + eu)*SGS + b] + sG2[( 8 + eu)*SGS + b] + sBias[ 8 + eu];
            float gg = sG[(16 + eu)*SGS + b] + sG2[(16 + eu)*SGS + b] + sBias[16 + eu];
            float go = sG[(24 + eu)*SGS + b] + sG2[(24 + eu)*SGS + b] + sBias[24 + eu];
            float iv = sigf(gi), fv = sigf(gf);
            float gv = tanhf_fast(gg), ov = sigf(go);
            float cold = half ? cB : cA;
            float hold = half ? hB : hA;
            float cn = fv*cold + iv*gv;
            float hn = ov*tanhf_fast(cn);
            float h2 = 0.5f*(hold + hn);     // K = 0.5 Euler blend
            float c2 = 0.5f*(cold + cn);
            if (half){ cB = c2; hB = h2; } else { cA = c2; hA = h2; }
            sHI[b*8 + eu]  = __float2half_rn(h2);
            sOUT[b*8 + eu] = h2;
            if (t == TT-1){
                out_final[(size_t)b*1024 +       U0 + eu] = h2;
                out_final[(size_t)b*1024 + 512 + U0 + eu] = c2;
            }
        }
        __syncthreads();

        // ---- publish next h image, then release flag, then off-path stores
        if (tid < BATCH){
            uint4 vh = *reinterpret_cast<uint4*>(sHI + tid*8);
            *reinterpret_cast<uint4*>(g_hh[par ^ 1] + (size_t)tid*HH + U0) = vh;
        }
        __syncthreads();
        if (t != TT-1 && tid == 0){
            asm volatile("st.release.gpu.global.u32 [%0], %1;"
                         :: "l"(&g_flags[blockIdx.x]), "r"((unsigned)(t+1)) : "memory");
        }
        if (tid < BATCH){
            float4 v0 = *reinterpret_cast<float4*>(sOUT + tid*8);
            float4 v1 = *reinterpret_cast<float4*>(sOUT + tid*8 + 4);
            float* dst = out_states + ((size_t)tid*TT + t)*HH + U0;
            *reinterpret_cast<float4*>(dst)     = v0;
            *reinterpret_cast<float4*>(dst + 4) = v1;
        }
    }
}

extern "C" void kernel_launch(void* const* d_in, const int* in_sizes, int n_in,
                              void* d_out, int out_size)
{
    const float* x    = (const float*)d_in[0];
    const float* W_ih = (const float*)d_in[1];
    const float* W_hh = (const float*)d_in[2];
    const float* b_ih = (const float*)d_in[3];
    const float* b_hh = (const float*)d_in[4];
    float* out        = (float*)d_out;
    float* out_final  = out + (size_t)BATCH*TT*HH;

    cudaFuncSetAttribute(stn_kernel, cudaFuncAttributeMaxDynamicSharedMemorySize, SMEM_TOTAL);
    stn_init_kernel<<<64, 128>>>();
    stn_kernel<<<GRID, NTH, SMEM_TOTAL>>>(x, W_ih, W_hh, b_ih, b_hh, out, out_final);
}

// round 13
// speedup vs baseline: 1.9161x; 1.1242x over previous
#include <cuda_runtime.h>
#include <cuda_fp16.h>
#include <cstdint>

#define TT 4096
#define BATCH 64
#define HH 512
#define GRID 64
#define NTH 256
#define RSB 1168        // A/B row stride bytes (584 halves, padded)

// smem byte offsets
#define OFF_BIAS 0              // 32 f32 = 128
#define OFF_P    128            // h2 half staging [64][8] = 1024
#define OFF_O    1152           // h2 f32 staging [64][8] = 2048
#define OFF_GO   3200           // 4 pairs x 8u x 17 float2 = 4352
#define OFF_A    7552           // [32][584] f16 = 37376
#define OFF_B    44928          // [64][584] f16 = 74752
#define SMEM_TOTAL 119680

__device__ __align__(16) __half g_hh[2][BATCH*HH];
__device__ int g_flags[GRID*32];     // padded: one 128B line per CTA

__device__ __forceinline__ float sigf(float x){ return 1.f/(1.f+__expf(-x)); }
__device__ __forceinline__ float tanhf_fast(float x){
    float e = __expf(-2.f*fabsf(x));
    return copysignf((1.f-e)/(1.f+e), x);
}
__device__ __forceinline__ unsigned pack2h(float a, float b){
    __half2 h = __floats2half2_rn(a, b);
    return *reinterpret_cast<unsigned*>(&h);
}
__device__ __forceinline__ void cp16(unsigned dst, const void* src){
    asm volatile("cp.async.cg.shared.global [%0], [%1], 16;\n"::"r"(dst),"l"(src));
}
__device__ __forceinline__ void cp_commit(){ asm volatile("cp.async.commit_group;\n"::); }
#define CP_WAIT(N) asm volatile("cp.async.wait_group %0;\n"::"n"(N))

__device__ __forceinline__ unsigned smem_u32(const void* p){
    unsigned a;
    asm("{ .reg .u64 t; cvta.to.shared.u64 t, %1; cvt.u32.u64 %0, t; }" : "=r"(a) : "l"(p));
    return a;
}
#define NBAR(id) asm volatile("bar.sync %0, 64;" :: "r"(id) : "memory")

#define LDSM4(r0,r1,r2,r3,addr) \
    asm volatile("ldmatrix.sync.aligned.m8n8.x4.shared.b16 {%0,%1,%2,%3}, [%4];" \
        : "=r"(r0),"=r"(r1),"=r"(r2),"=r"(r3) : "r"(addr))

#define MMA16816(d,a0,a1,a2,a3,b0,b1) \
    asm volatile("mma.sync.aligned.m16n8k16.row.col.f32.f16.f16.f32 " \
        "{%0,%1,%2,%3}, {%4,%5,%6,%7}, {%8,%9}, {%0,%1,%2,%3};" \
        : "+f"((d)[0]),"+f"((d)[1]),"+f"((d)[2]),"+f"((d)[3]) \
        : "r"(a0),"r"(a1),"r"(a2),"r"(a3),"r"(b0),"r"(b1))

__global__ void __launch_bounds__(128,1) stn_init_kernel(){
    int i = blockIdx.x*blockDim.x + threadIdx.x;
    if (i < 2*BATCH*HH/8)
        reinterpret_cast<uint4*>(g_hh)[i] = make_uint4(0,0,0,0);
    if (i < GRID*32) g_flags[i] = 0;
}

__device__ __forceinline__ void poll_flag(const int* fp, unsigned t){
    unsigned v;
    do {
        asm volatile("ld.relaxed.gpu.global.u32 %0, [%1];" : "=r"(v) : "l"(fp) : "memory");
    } while (v < t);
}

__global__ void __launch_bounds__(NTH,1) stn_kernel(
    const float* __restrict__ x,      // [64,4096,64]
    const float* __restrict__ W_ih,   // [2048,64]
    const float* __restrict__ W_hh,   // [2048,512]
    const float* __restrict__ b_ih,
    const float* __restrict__ b_hh,
    float* __restrict__ out_states,   // [64,4096,512]
    float* __restrict__ out_final)    // [64,1024]
{
    extern __shared__ __align__(16) unsigned char smem[];
    float*  sBias = reinterpret_cast<float*>(smem + OFF_BIAS);
    __half* sHI   = reinterpret_cast<__half*>(smem + OFF_P);
    float*  sOUT  = reinterpret_cast<float*>(smem + OFF_O);
    const unsigned S = smem_u32(smem);
    const unsigned sB = S + OFF_B;

    const int tid  = threadIdx.x;
    const int lane = tid & 31, warp = tid >> 5;
    const int U0   = blockIdx.x * 8;

    // ---- weights once: local row r = gate*8+u -> global row gate*512 + U0 + u
    for (int idx = tid; idx < 32*72; idx += NTH){
        int r = idx / 72, c8 = (idx - r*72) * 8;
        int R = (r >> 3)*HH + U0 + (r & 7);
        const float* src = (c8 < HH) ? (W_hh + (size_t)R*HH + c8)
                                     : (W_ih + R*64 + (c8 - HH));
        float4 v0 = *reinterpret_cast<const float4*>(src);
        float4 v1 = *reinterpret_cast<const float4*>(src + 4);
        uint4 pk;
        pk.x = pack2h(v0.x, v0.y); pk.y = pack2h(v0.z, v0.w);
        pk.z = pack2h(v1.x, v1.y); pk.w = pack2h(v1.z, v1.w);
        *reinterpret_cast<uint4*>(smem + OFF_A + r*RSB + c8*2) = pk;
    }
    if (tid < 32){
        int R = (tid >> 3)*HH + U0 + (tid & 7);
        sBias[tid] = b_ih[R] + b_hh[R];
    }
    __syncthreads();

    // ---- warp roles (R10 tiling): mrow0 in {0 (i,f), 16 (g,o)}, nc0 = N tile
    const int pair  = warp & 3;
    const int isGO  = warp >> 2;
    const int mrow0 = isGO * 16;
    const int nc0   = pair * 16;
    const unsigned aAddr = S + OFF_A + (unsigned)(mrow0 + (lane & 15))*RSB + (lane >> 4)*16;
    const unsigned bAddr = sB + (unsigned)(nc0 + (lane & 15))*RSB + (lane >> 4)*16;

    // gate exchange region for this pair
    float* sGO = reinterpret_cast<float*>(smem + OFF_GO + pair*1088);
    const int eu = lane >> 2;                   // unit 0..7
    const int cb0 = (lane & 3)*2;               // col-in-tile base

    const int bx = tid >> 2, q = tid & 3;       // x staging roles

    float cC[4] = {0.f,0.f,0.f,0.f};
    float hC[4] = {0.f,0.f,0.f,0.f};

    for (int t = 0; t < TT; ++t){
        const int par = t & 1;
        const __half* hsrc = g_hh[par];

        // ---- x load + stage into B cols 512..575 (B free after prior MMA)
        {
            const float* xp = x + ((size_t)bx*TT + t)*64 + q*16;
            float4 xa = *reinterpret_cast<const float4*>(xp);
            float4 xb = *reinterpret_cast<const float4*>(xp + 4);
            float4 xc = *reinterpret_cast<const float4*>(xp + 8);
            float4 xd = *reinterpret_cast<const float4*>(xp + 12);
            uint4 p0, p1;
            p0.x = pack2h(xa.x,xa.y); p0.y = pack2h(xa.z,xa.w);
            p0.z = pack2h(xb.x,xb.y); p0.w = pack2h(xb.z,xb.w);
            p1.x = pack2h(xc.x,xc.y); p1.y = pack2h(xc.z,xc.w);
            p1.z = pack2h(xd.x,xd.y); p1.w = pack2h(xd.z,xd.w);
            unsigned char* dst = smem + OFF_B + (unsigned)bx*RSB + 1024 + q*32;
            *reinterpret_cast<uint4*>(dst)      = p0;
            *reinterpret_cast<uint4*>(dst + 16) = p1;
        }

        // ---- poll lower 32 producer flags (units 0..255)
        if (t && tid < 32) poll_flag(&g_flags[tid*32], (unsigned)t);
        __syncthreads();
        if (t && tid == 0) asm volatile("fence.acq_rel.gpu;" ::: "memory");
        // (fence by poller thread 0 isn't enough for others' cp -> use per-thread fence)
        asm volatile("fence.acq_rel.gpu;" ::: "memory");

        // ---- cp chunk0: cols 0..255
        {
#pragma unroll
            for (int i = 0; i < 8; ++i){
                int idx = i*NTH + tid;
                int b = idx >> 5, ch = idx & 31;
                cp16(sB + (unsigned)b*RSB + ch*16, reinterpret_cast<const unsigned char*>(hsrc) + (size_t)b*1024 + ch*16);
            }
            cp_commit();
        }
        // ---- poll upper 32 flags while chunk0 flies
        if (t && tid < 32) poll_flag(&g_flags[(32+tid)*32], (unsigned)t);
        __syncthreads();
        asm volatile("fence.acq_rel.gpu;" ::: "memory");
        // ---- cp chunk1: cols 256..511
        {
#pragma unroll
            for (int i = 0; i < 8; ++i){
                int idx = i*NTH + tid;
                int b = idx >> 5, ch = idx & 31;
                cp16(sB + (unsigned)b*RSB + 512 + ch*16, reinterpret_cast<const unsigned char*>(hsrc) + (size_t)b*1024 + 512 + ch*16);
            }
            cp_commit();
        }

        float d0[4] = {0.f,0.f,0.f,0.f};
        float d1[4] = {0.f,0.f,0.f,0.f};

        // ---- x-MMA first (cols 512..575, no cp dependency)
#pragma unroll
        for (int ks = 32; ks < 36; ++ks){
            unsigned a0,a1,a2,a3,b0,b1,b2,b3;
            LDSM4(a0,a1,a2,a3, aAddr + ks*32);
            LDSM4(b0,b1,b2,b3, bAddr + ks*32);
            MMA16816(d0, a0,a1,a2,a3, b0,b2);
            MMA16816(d1, a0,a1,a2,a3, b1,b3);
        }
        CP_WAIT(1);
        __syncthreads();
#pragma unroll
        for (int ks = 0; ks < 16; ++ks){
            unsigned a0,a1,a2,a3,b0,b1,b2,b3;
            LDSM4(a0,a1,a2,a3, aAddr + ks*32);
            LDSM4(b0,b1,b2,b3, bAddr + ks*32);
            MMA16816(d0, a0,a1,a2,a3, b0,b2);
            MMA16816(d1, a0,a1,a2,a3, b1,b3);
        }
        CP_WAIT(0);
        __syncthreads();
#pragma unroll
        for (int ks = 16; ks < 32; ++ks){
            unsigned a0,a1,a2,a3,b0,b1,b2,b3;
            LDSM4(a0,a1,a2,a3, aAddr + ks*32);
            LDSM4(b0,b1,b2,b3, bAddr + ks*32);
            MMA16816(d0, a0,a1,a2,a3, b0,b2);
            MMA16816(d1, a0,a1,a2,a3, b1,b3);
        }

        // ---- g,o warps export fragments (interleaved {g,o} float2 per (u,col))
        if (isGO){
            float* base = sGO + eu*34;          // 136B / 4
            *reinterpret_cast<float2*>(base + (cb0    )*2) = make_float2(d0[0], d0[2]);
            *reinterpret_cast<float2*>(base + (cb0 + 1)*2) = make_float2(d0[1], d0[3]);
            *reinterpret_cast<float2*>(base + (cb0 + 8)*2) = make_float2(d1[0], d1[2]);
            *reinterpret_cast<float2*>(base + (cb0 + 9)*2) = make_float2(d1[1], d1[3]);
        }
        NBAR(pair + 1);

        // ---- epilogue (i,f warps): 4 cells from own regs + pair's g,o
        if (!isGO){
            float iv[4] = {d0[0], d0[1], d1[0], d1[1]};
            float fv[4] = {d0[2], d0[3], d1[2], d1[3]};
            const int cols[4] = {cb0, cb0+1, cb0+8, cb0+9};
            float bi = sBias[eu], bf = sBias[8+eu], bg = sBias[16+eu], bo = sBias[24+eu];
            float* base = sGO + eu*34;
#pragma unroll
            for (int j = 0; j < 4; ++j){
                float2 go = *reinterpret_cast<float2*>(base + cols[j]*2);
                float ii = sigf(iv[j] + bi);
                float ff = sigf(fv[j] + bf);
                float gg = tanhf_fast(go.x + bg);
                float oo = sigf(go.y + bo);
                float cn = ff*cC[j] + ii*gg;
                float hn = oo*tanhf_fast(cn);
                float h2 = 0.5f*(hC[j] + hn);      // K = 0.5
                float c2 = 0.5f*(cC[j] + cn);
                cC[j] = c2; hC[j] = h2;
                int b = nc0 + cols[j];
                sHI[b*8 + eu]  = __float2half_rn(h2);
                sOUT[b*8 + eu] = h2;
                if (t == TT-1){
                    out_final[(size_t)b*1024 +       U0 + eu] = h2;
                    out_final[(size_t)b*1024 + 512 + U0 + eu] = c2;
                }
            }
        }
        __syncthreads();

        // ---- specialized tail: w4,5 publish+release; w6,7 out_states; w0-3 loop on
        if (warp == 4 || warp == 5){
            int b = tid - 128;
            uint4 vh = *reinterpret_cast<uint4*>(sHI + b*8);
            *reinterpret_cast<uint4*>(g_hh[par ^ 1] + (size_t)b*HH + U0) = vh;
            NBAR(5);
            if (tid == 128 && t != TT-1){
                asm volatile("st.release.gpu.global.u32 [%0], %1;"
                             :: "l"(&g_flags[blockIdx.x*32]), "r"((unsigned)(t+1)) : "memory");
            }
        } else if (warp >= 6){
            int b = tid - 192;
            float4 v0 = *reinterpret_cast<float4*>(sOUT + b*8);
            float4 v1 = *reinterpret_cast<float4*>(sOUT + b*8 + 4);
            float* dst = out_states + ((size_t)b*TT + t)*HH + U0;
            *reinterpret_cast<float4*>(dst)     = v0;
            *reinterpret_cast<float4*>(dst + 4) = v1;
        }
    }
}

extern "C" void kernel_launch(void* const* d_in, const int* in_sizes, int n_in,
                              void* d_out, int out_size)
{
    const float* x    = (const float*)d_in[0];
    const float* W_ih = (const float*)d_in[1];
    const float* W_hh = (const float*)d_in[2];
    const float* b_ih = (const float*)d_in[3];
    const float* b_hh = (const float*)d_in[4];
    float* out        = (float*)d_out;
    float* out_final  = out + (size_t)BATCH*TT*HH;

    cudaFuncSetAttribute(stn_kernel, cudaFuncAttributeMaxDynamicSharedMemorySize, SMEM_TOTAL);
    stn_init_kernel<<<64, 128>>>();
    stn_kernel<<<GRID, NTH, SMEM_TOTAL>>>(x, W_ih, W_hh, b_ih, b_hh, out, out_final);
}

// round 17
// speedup vs baseline: 2.8128x; 1.4679x over previous
#include <cuda_runtime.h>
#include <cuda_fp16.h>
#include <cstdint>

#define TT 4096
#define BATCH 64
#define HH 512
#define GRID 64
#define NTH 256
#define RSB 1168        // A row stride bytes (584 halves, padded)
#define XSTR 144        // x staging row stride bytes (MULTIPLE OF 16 for ldmatrix)

// smem byte offsets
#define OFF_BIAS 0              // 32 f32 = 128
#define OFF_O    128            // h2 f32 staging [64][8] = 2048
#define OFF_GO   2176           // 4 pairs x 1088B = 4352
#define OFF_A    6528           // [32][584] f16 = 37376
#define OFF_X    43904          // [64][144B] = 9216
#define SMEM_TOTAL 53120

// h images in B-fragment layout: [parity][(pair*32 + ks)*32 + lane] -> uint4
__device__ __align__(16) uint4 g_hfrag[2][4096];
__device__ int g_flags[GRID];

__device__ __forceinline__ float sigf(float x){ return 1.f/(1.f+__expf(-x)); }
__device__ __forceinline__ float tanhf_fast(float x){
    float e = __expf(-2.f*fabsf(x));
    return copysignf((1.f-e)/(1.f+e), x);
}
__device__ __forceinline__ unsigned pack2h(float a, float b){
    __half2 h = __floats2half2_rn(a, b);
    return *reinterpret_cast<unsigned*>(&h);
}
__device__ __forceinline__ unsigned smem_u32(const void* p){
    unsigned a;
    asm("{ .reg .u64 t; cvta.to.shared.u64 t, %1; cvt.u32.u64 %0, t; }" : "=r"(a) : "l"(p));
    return a;
}
__device__ __forceinline__ uint4 ldg_cg_v4(const uint4* p){
    uint4 v;
    asm volatile("ld.global.cg.v4.u32 {%0,%1,%2,%3}, [%4];"
                 : "=r"(v.x),"=r"(v.y),"=r"(v.z),"=r"(v.w) : "l"(p));
    return v;
}
__device__ __forceinline__ void stg_cg_u32(unsigned* p, unsigned v){
    asm volatile("st.global.cg.u32 [%0], %1;" :: "l"(p), "r"(v) : "memory");
}
#define NBAR(id) asm volatile("bar.sync %0, 64;" :: "r"(id) : "memory")

#define LDSM4(r0,r1,r2,r3,addr) \
    asm volatile("ldmatrix.sync.aligned.m8n8.x4.shared.b16 {%0,%1,%2,%3}, [%4];" \
        : "=r"(r0),"=r"(r1),"=r"(r2),"=r"(r3) : "r"(addr))

#define MMA16816(d,a0,a1,a2,a3,b0,b1) \
    asm volatile("mma.sync.aligned.m16n8k16.row.col.f32.f16.f16.f32 " \
        "{%0,%1,%2,%3}, {%4,%5,%6,%7}, {%8,%9}, {%0,%1,%2,%3};" \
        : "+f"((d)[0]),"+f"((d)[1]),"+f"((d)[2]),"+f"((d)[3]) \
        : "r"(a0),"r"(a1),"r"(a2),"r"(a3),"r"(b0),"r"(b1))

__global__ void __launch_bounds__(128,1) stn_init_kernel(){
    int i = blockIdx.x*blockDim.x + threadIdx.x;
    if (i < 2*4096){
        reinterpret_cast<uint4*>(g_hfrag)[i] = make_uint4(0,0,0,0);
    }
    if (i < GRID) g_flags[i] = 0;
}

__global__ void __launch_bounds__(NTH,1) stn_kernel(
    const float* __restrict__ x,      // [64,4096,64]
    const float* __restrict__ W_ih,   // [2048,64]
    const float* __restrict__ W_hh,   // [2048,512]
    const float* __restrict__ b_ih,
    const float* __restrict__ b_hh,
    float* __restrict__ out_states,   // [64,4096,512]
    float* __restrict__ out_final)    // [64,1024]
{
    extern __shared__ __align__(16) unsigned char smem[];
    float* sBias = reinterpret_cast<float*>(smem + OFF_BIAS);
    float* sOUT  = reinterpret_cast<float*>(smem + OFF_O);
    const unsigned S = smem_u32(smem);

    const int tid  = threadIdx.x;
    const int lane = tid & 31, warp = tid >> 5;
    const int U0   = blockIdx.x * 8;

    // ---- weights once: local row r = gate*8+u -> global row gate*512 + U0 + u
    for (int idx = tid; idx < 32*72; idx += NTH){
        int r = idx / 72, c8 = (idx - r*72) * 8;
        int R = (r >> 3)*HH + U0 + (r & 7);
        const float* src = (c8 < HH) ? (W_hh + (size_t)R*HH + c8)
                                     : (W_ih + R*64 + (c8 - HH));
        float4 v0 = *reinterpret_cast<const float4*>(src);
        float4 v1 = *reinterpret_cast<const float4*>(src + 4);
        uint4 pk;
        pk.x = pack2h(v0.x, v0.y); pk.y = pack2h(v0.z, v0.w);
        pk.z = pack2h(v1.x, v1.y); pk.w = pack2h(v1.z, v1.w);
        *reinterpret_cast<uint4*>(smem + OFF_A + r*RSB + c8*2) = pk;
    }
    if (tid < 32){
        int R = (tid >> 3)*HH + U0 + (tid & 7);
        sBias[tid] = b_ih[R] + b_hh[R];
    }
    __syncthreads();

    // ---- warp roles: pair = N tile (16 batches), isGO selects gate rows
    const int pair  = warp & 3;
    const int isGO  = warp >> 2;
    const int mrow0 = isGO * 16;
    const int nc0   = pair * 16;
    const unsigned aAddr = S + OFF_A + (unsigned)(mrow0 + (lane & 15))*RSB + (lane >> 4)*16;
    const unsigned xAddr = S + OFF_X + (unsigned)(nc0 + (lane & 15))*XSTR + (lane >> 4)*16;

    float* sGO = reinterpret_cast<float*>(smem + OFF_GO + pair*1088);
    const int eu  = lane >> 2;           // unit 0..7
    const int cb0 = (lane & 3)*2;        // col base in n-tile

    const int bx = tid >> 2, q = tid & 3;       // x staging roles
    const int ksU  = U0 >> 4;            // this CTA's unit block
    const int half = (U0 >> 3) & 1;      // low/high half of the block

    float cC[4] = {0.f,0.f,0.f,0.f};
    float hC[4] = {0.f,0.f,0.f,0.f};

    for (int t = 0; t < TT; ++t){
        const int par = t & 1;

        // ---- x prefetch (hides DRAM latency behind the barrier)
        const float* xp = x + ((size_t)bx*TT + t)*64 + q*16;
        float4 xa = *reinterpret_cast<const float4*>(xp);
        float4 xb = *reinterpret_cast<const float4*>(xp + 4);
        float4 xc = *reinterpret_cast<const float4*>(xp + 8);
        float4 xd = *reinterpret_cast<const float4*>(xp + 12);

        // ---- grid-wide step barrier (R10 pattern: acquire loads)
        if (t){
            if (tid < GRID){
                unsigned v;
                const int* fp = &g_flags[tid];
                do {
                    asm volatile("ld.acquire.gpu.global.u32 %0,[%1];" : "=r"(v) : "l"(fp) : "memory");
                } while (v < (unsigned)t);
            }
            __syncthreads();
        }

        // ---- start h-fragment loads (pipeline prime)
        const uint4* hp = &g_hfrag[par][(pair*32)*32 + lane];
        uint4 f[4];
#pragma unroll
        for (int i = 0; i < 4; ++i) f[i] = ldg_cg_v4(hp + i*32);

        // ---- stage x (A cols 512..575)
        {
            uint4 p0, p1;
            p0.x = pack2h(xa.x,xa.y); p0.y = pack2h(xa.z,xa.w);
            p0.z = pack2h(xb.x,xb.y); p0.w = pack2h(xb.z,xb.w);
            p1.x = pack2h(xc.x,xc.y); p1.y = pack2h(xc.z,xc.w);
            p1.z = pack2h(xd.x,xd.y); p1.w = pack2h(xd.z,xd.w);
            unsigned char* dst = smem + OFF_X + (unsigned)bx*XSTR + q*32;
            *reinterpret_cast<uint4*>(dst)      = p0;
            *reinterpret_cast<uint4*>(dst + 16) = p1;
        }
        __syncthreads();

        float d0[4] = {0.f,0.f,0.f,0.f};
        float d1[4] = {0.f,0.f,0.f,0.f};

        // ---- x-MMA (k-steps 32..35) while h fragments arrive
#pragma unroll
        for (int ks2 = 0; ks2 < 4; ++ks2){
            unsigned a0,a1,a2,a3,b0,b1,b2,b3;
            LDSM4(a0,a1,a2,a3, aAddr + (32+ks2)*32);
            LDSM4(b0,b1,b2,b3, xAddr + ks2*32);
            MMA16816(d0, a0,a1,a2,a3, b0,b2);
            MMA16816(d1, a0,a1,a2,a3, b1,b3);
        }

        // ---- h-MMA: 32 k-steps, B direct from global (pipelined depth 4)
#pragma unroll
        for (int ks = 0; ks < 32; ++ks){
            unsigned a0,a1,a2,a3;
            LDSM4(a0,a1,a2,a3, aAddr + ks*32);
            uint4 b = f[ks & 3];
            if (ks + 4 < 32) f[ks & 3] = ldg_cg_v4(hp + (ks+4)*32);
            MMA16816(d0, a0,a1,a2,a3, b.x, b.z);
            MMA16816(d1, a0,a1,a2,a3, b.y, b.w);
        }

        // ---- g,o warps export fragments for the pair
        if (isGO){
            float* base = sGO + eu*34;
            *reinterpret_cast<float2*>(base + (cb0    )*2) = make_float2(d0[0], d0[2]);
            *reinterpret_cast<float2*>(base + (cb0 + 1)*2) = make_float2(d0[1], d0[3]);
            *reinterpret_cast<float2*>(base + (cb0 + 8)*2) = make_float2(d1[0], d1[2]);
            *reinterpret_cast<float2*>(base + (cb0 + 9)*2) = make_float2(d1[1], d1[3]);
        }
        NBAR(pair + 1);

        // ---- epilogue (i,f warps): cells + direct fragment publish
        if (!isGO){
            float iv[4] = {d0[0], d0[1], d1[0], d1[1]};
            float fv[4] = {d0[2], d0[3], d1[2], d1[3]};
            const int cols[4] = {cb0, cb0+1, cb0+8, cb0+9};
            float bi = sBias[eu], bf = sBias[8+eu], bg = sBias[16+eu], bo = sBias[24+eu];
            float* base = sGO + eu*34;
            float h2v[4];
#pragma unroll
            for (int j = 0; j < 4; ++j){
                float2 go = *reinterpret_cast<float2*>(base + cols[j]*2);
                float ii = sigf(iv[j] + bi);
                float ff = sigf(fv[j] + bf);
                float gg = tanhf_fast(go.x + bg);
                float oo = sigf(go.y + bo);
                float cn = ff*cC[j] + ii*gg;
                float hn = oo*tanhf_fast(cn);
                float h2 = 0.5f*(hC[j] + hn);     // K = 0.5
                float c2 = 0.5f*(cC[j] + cn);
                cC[j] = c2; hC[j] = h2; h2v[j] = h2;
                int b = nc0 + cols[j];
                sOUT[b*8 + eu] = h2;
                if (t == TT-1){
                    out_final[(size_t)b*1024 +       U0 + eu] = h2;
                    out_final[(size_t)b*1024 + 512 + U0 + eu] = c2;
                }
            }
            // pair units (eu with eu^1) via shuffle, publish 4 STG.32 in frag layout
            float h2p[4];
#pragma unroll
            for (int j = 0; j < 4; ++j)
                h2p[j] = __shfl_xor_sync(0xffffffffu, h2v[j], 4);
            if ((eu & 1) == 0){
                unsigned* dst0 = reinterpret_cast<unsigned*>(
                    &g_hfrag[par ^ 1][(pair*32 + ksU)*32]);
#pragma unroll
                for (int j = 0; j < 4; ++j){
                    int n16 = cols[j];
                    int l   = (n16 & 7)*4 + (eu >> 1);
                    int rj  = half*2 + (n16 >> 3);
                    stg_cg_u32(dst0 + l*4 + rj, pack2h(h2v[j], h2p[j]));
                }
            }
        }
        __syncthreads();

        // ---- release flag, then off-path output stores
        if (t != TT-1 && tid == 0){
            asm volatile("st.release.gpu.global.u32 [%0], %1;"
                         :: "l"(&g_flags[blockIdx.x]), "r"((unsigned)(t+1)) : "memory");
        }
        if (tid < BATCH){
            float4 v0 = *reinterpret_cast<float4*>(sOUT + tid*8);
            float4 v1 = *reinterpret_cast<float4*>(sOUT + tid*8 + 4);
            float* dst = out_states + ((size_t)tid*TT + t)*HH + U0;
            *reinterpret_cast<float4*>(dst)     = v0;
            *reinterpret_cast<float4*>(dst + 4) = v1;
        }
    }
}

extern "C" void kernel_launch(void* const* d_in, const int* in_sizes, int n_in,
                              void* d_out, int out_size)
{
    const float* x    = (const float*)d_in[0];
    const float* W_ih = (const float*)d_in[1];
    const float* W_hh = (const float*)d_in[2];
    const float* b_ih = (const float*)d_in[3];
    const float* b_hh = (const float*)d_in[4];
    float* out        = (float*)d_out;
    float* out_final  = out + (size_t)BATCH*TT*HH;

    cudaFuncSetAttribute(stn_kernel, cudaFuncAttributeMaxDynamicSharedMemorySize, SMEM_TOTAL);
    stn_init_kernel<<<64, 128>>>();
    stn_kernel<<<GRID, NTH, SMEM_TOTAL>>>(x, W_ih, W_hh, b_ih, b_hh, out, out_final);
}